// round 4
// baseline (speedup 1.0000x reference)
#include <cuda_runtime.h>
#include <math.h>

#define NMAX 100000
#define EMAX 1600000
#define FD 128
#define HD 128
#define CD 40
#define NLAY 4

// ---- static device scratch ----
// Invariant: g_cnt, g_stats, g_done are zero at entry of every kernel_launch
// call (zero at module load; each call re-zeroes them after use).
__device__ float g_xw[(size_t)NMAX * HD];
__device__ float g_agg[NLAY][(size_t)NMAX * HD];
__device__ int   g_cnt[NMAX];
__device__ float g_dinv[NMAX];
__device__ int   g_off[NMAX + 1];
__device__ int   g_cur[NMAX];
__device__ int   g_csrc[EMAX];
__device__ float g_cval[EMAX];
__device__ float g_stats[NLAY][2 * HD];
__device__ float g_scale[NLAY][HD];
__device__ float g_sbias[NLAY][HD];
__device__ int   g_done[NLAY];

// ---- packed f32x2 helpers ----
__device__ __forceinline__ unsigned long long pk2(float lo, float hi) {
    unsigned long long r;
    asm("mov.b64 %0, {%1, %2};" : "=l"(r) : "f"(lo), "f"(hi));
    return r;
}
__device__ __forceinline__ void fma2(unsigned long long& d,
                                     unsigned long long a, unsigned long long b) {
    asm("fma.rn.f32x2 %0, %1, %2, %0;" : "+l"(d) : "l"(a), "l"(b));
}
__device__ __forceinline__ float2 up2(unsigned long long v) {
    float2 r;
    asm("mov.b64 {%0, %1}, %2;" : "=f"(r.x), "=f"(r.y) : "l"(v));
    return r;
}

// ---------------------------------------------------------------------------
// single-block scan: offsets, cursor init, dinv; zeroes g_cnt for next replay
__global__ void k_scan(int n) {
    __shared__ int sp[1024];
    int t = threadIdx.x;
    int chunk = (n + 1023) >> 10;
    int beg = t * chunk;
    int end = min(beg + chunk, n);
    int s = 0;
    for (int j = beg; j < end; j++) s += g_cnt[j];
    sp[t] = s;
    __syncthreads();
    for (int d = 1; d < 1024; d <<= 1) {
        int tmp = (t >= d) ? sp[t - d] : 0;
        __syncthreads();
        sp[t] += tmp;
        __syncthreads();
    }
    int base = sp[t] - s;
    for (int j = beg; j < end; j++) {
        int c = g_cnt[j];
        g_cnt[j] = 0;  // self-reset
        g_off[j] = base;
        g_cur[j] = base;
        g_dinv[j] = rsqrtf((float)c + 2.0f);
        base += c;
    }
    if (end == n) g_off[n] = base;
}

__global__ void k_fill(const int* __restrict__ src, const int* __restrict__ dst, int e) {
    int i = blockIdx.x * blockDim.x + threadIdx.x;
    if (i < e) {
        int d = dst[i];
        int s = src[i];
        int p = atomicAdd(&g_cur[d], 1);
        g_csrc[p] = s;
        g_cval[p] = g_dinv[s];
    }
}

// ---------------------------------------------------------------------------
// SGEMM: g_xw[n,128] = A[n,128] @ W[128,128], double-buffered BK=16 pipeline.
// A = x (layer 0) or relu(g_agg[layer-1]*scale+bias) fused on load.
// Layer 0 variant carries extra grid-stride blocks doing the degree histogram
// (overlaps graph preprocessing with the first GEMM).
__global__ __launch_bounds__(256, 2) void k_gemm(const float* __restrict__ x,
                                                 const float* __restrict__ W,
                                                 int layer, int n, int gemm_blocks,
                                                 const int* __restrict__ hist_dst, int e) {
    if ((int)blockIdx.x >= gemm_blocks) {
        // histogram side-blocks (layer 0 only)
        int nthr = (gridDim.x - gemm_blocks) * blockDim.x;
        int i0 = (blockIdx.x - gemm_blocks) * blockDim.x + threadIdx.x;
        for (int i = i0; i < e; i += nthr) atomicAdd(&g_cnt[hist_dst[i]], 1);
        return;
    }
    __shared__ __align__(16) float As[2][16][128];
    __shared__ __align__(16) float Bs[2][16][128];
    const float* A  = (layer == 0) ? x : g_agg[layer - 1];
    const float* sc = (layer > 0) ? g_scale[layer - 1] : 0;
    const float* sb = (layer > 0) ? g_sbias[layer - 1] : 0;
    int tid  = threadIdx.x;
    int ar = tid >> 1, akq = (tid & 1) * 8;
    int bkr = tid >> 4, bc = (tid & 15) * 8;
    int trow = tid >> 4, tcol = tid & 15;
    int row0 = blockIdx.x * 128;
    int gr = row0 + ar;

    unsigned long long acc2[8][4];
#pragma unroll
    for (int m = 0; m < 8; m++)
#pragma unroll
        for (int q = 0; q < 4; q++) acc2[m][q] = 0ull;

    float4 pa[2], pb[2];
    {
        pa[0] = make_float4(0.f, 0.f, 0.f, 0.f);
        pa[1] = pa[0];
        if (gr < n) {
            pa[0] = *(const float4*)(A + (size_t)gr * HD + akq);
            pa[1] = *(const float4*)(A + (size_t)gr * HD + akq + 4);
        }
        pb[0] = *(const float4*)(W + (size_t)bkr * HD + bc);
        pb[1] = *(const float4*)(W + (size_t)bkr * HD + bc + 4);
        if (layer > 0) {
#pragma unroll
            for (int h = 0; h < 2; h++) {
                int kb = akq + h * 4;
                float* p = (float*)&pa[h];
                p[0] = fmaxf(fmaf(p[0], sc[kb + 0], sb[kb + 0]), 0.f);
                p[1] = fmaxf(fmaf(p[1], sc[kb + 1], sb[kb + 1]), 0.f);
                p[2] = fmaxf(fmaf(p[2], sc[kb + 2], sb[kb + 2]), 0.f);
                p[3] = fmaxf(fmaf(p[3], sc[kb + 3], sb[kb + 3]), 0.f);
            }
        }
#pragma unroll
        for (int h = 0; h < 2; h++) {
            float* p = (float*)&pa[h];
            As[0][akq + h * 4 + 0][ar] = p[0];
            As[0][akq + h * 4 + 1][ar] = p[1];
            As[0][akq + h * 4 + 2][ar] = p[2];
            As[0][akq + h * 4 + 3][ar] = p[3];
        }
        *(float4*)&Bs[0][bkr][bc]     = pb[0];
        *(float4*)&Bs[0][bkr][bc + 4] = pb[1];
    }
    __syncthreads();

#pragma unroll
    for (int ks = 0; ks < 8; ks++) {
        int buf = ks & 1;
        if (ks < 7) {
            int k0 = (ks + 1) * 16;
            pa[0] = make_float4(0.f, 0.f, 0.f, 0.f);
            pa[1] = pa[0];
            if (gr < n) {
                pa[0] = *(const float4*)(A + (size_t)gr * HD + k0 + akq);
                pa[1] = *(const float4*)(A + (size_t)gr * HD + k0 + akq + 4);
            }
            pb[0] = *(const float4*)(W + (size_t)(k0 + bkr) * HD + bc);
            pb[1] = *(const float4*)(W + (size_t)(k0 + bkr) * HD + bc + 4);
            if (layer > 0) {
#pragma unroll
                for (int h = 0; h < 2; h++) {
                    int kb = k0 + akq + h * 4;
                    float* p = (float*)&pa[h];
                    p[0] = fmaxf(fmaf(p[0], sc[kb + 0], sb[kb + 0]), 0.f);
                    p[1] = fmaxf(fmaf(p[1], sc[kb + 1], sb[kb + 1]), 0.f);
                    p[2] = fmaxf(fmaf(p[2], sc[kb + 2], sb[kb + 2]), 0.f);
                    p[3] = fmaxf(fmaf(p[3], sc[kb + 3], sb[kb + 3]), 0.f);
                }
            }
        }
#pragma unroll
        for (int k = 0; k < 16; k++) {
            float4 ra0 = *(const float4*)&As[buf][k][trow * 8];
            float4 ra1 = *(const float4*)&As[buf][k][trow * 8 + 4];
            ulonglong2 b01 = *(const ulonglong2*)&Bs[buf][k][tcol * 8];
            ulonglong2 b23 = *(const ulonglong2*)&Bs[buf][k][tcol * 8 + 4];
            unsigned long long b2[4] = {b01.x, b01.y, b23.x, b23.y};
            float ra[8] = {ra0.x, ra0.y, ra0.z, ra0.w, ra1.x, ra1.y, ra1.z, ra1.w};
#pragma unroll
            for (int m = 0; m < 8; m++) {
                unsigned long long ad = pk2(ra[m], ra[m]);
#pragma unroll
                for (int q = 0; q < 4; q++) fma2(acc2[m][q], ad, b2[q]);
            }
        }
        if (ks < 7) {
            int nb = buf ^ 1;
#pragma unroll
            for (int h = 0; h < 2; h++) {
                float* p = (float*)&pa[h];
                As[nb][akq + h * 4 + 0][ar] = p[0];
                As[nb][akq + h * 4 + 1][ar] = p[1];
                As[nb][akq + h * 4 + 2][ar] = p[2];
                As[nb][akq + h * 4 + 3][ar] = p[3];
            }
            *(float4*)&Bs[nb][bkr][bc]     = pb[0];
            *(float4*)&Bs[nb][bkr][bc + 4] = pb[1];
            __syncthreads();
        }
    }
#pragma unroll
    for (int m = 0; m < 8; m++) {
        int r = row0 + trow * 8 + m;
        if (r < n) {
            float2 c0 = up2(acc2[m][0]), c1 = up2(acc2[m][1]);
            float2 c2 = up2(acc2[m][2]), c3 = up2(acc2[m][3]);
            *(float4*)(g_xw + (size_t)r * HD + tcol * 8) =
                make_float4(c0.x, c0.y, c1.x, c1.y);
            *(float4*)(g_xw + (size_t)r * HD + tcol * 8 + 4) =
                make_float4(c2.x, c2.y, c3.x, c3.y);
        }
    }
}

// ---------------------------------------------------------------------------
// Aggregation: warp per node; lane owns 4 columns. Unroll-8 gather (MLP=8),
// contiguous csrc/cval streams. BN stats + fused scale/bias in last block.
__global__ __launch_bounds__(256) void k_agg(int layer, const float* __restrict__ convb,
                                             const float* __restrict__ bn_g,
                                             const float* __restrict__ bn_b, int n) {
    __shared__ float s_sum[128], s_sq[128];
    __shared__ int s_last;
    int tid = threadIdx.x;
    if (tid < 128) { s_sum[tid] = 0.f; s_sq[tid] = 0.f; }
    __syncthreads();

    int lane = tid & 31;
    int warp = tid >> 5;
    int c4 = lane * 4;
    float4 b4 = *(const float4*)(convb + c4);
    float* out = g_agg[layer];

    int gw = blockIdx.x * 8 + warp;
    int nw = gridDim.x * 8;

    float ls0 = 0.f, ls1 = 0.f, ls2 = 0.f, ls3 = 0.f;
    float lq0 = 0.f, lq1 = 0.f, lq2 = 0.f, lq3 = 0.f;

    for (int v = gw; v < n; v += nw) {
        int r0 = g_off[v], r1 = g_off[v + 1];
        float dv = g_dinv[v];
        unsigned long long p0 = 0ull, p1 = 0ull;
        int j = r0;
        for (; j + 7 < r1; j += 8) {
            int   si[8];
            float wi[8];
#pragma unroll
            for (int u = 0; u < 8; u++) { si[u] = g_csrc[j + u]; wi[u] = g_cval[j + u]; }
            float4 xv[8];
#pragma unroll
            for (int u = 0; u < 8; u++)
                xv[u] = *(const float4*)(g_xw + (size_t)si[u] * HD + c4);
#pragma unroll
            for (int u = 0; u < 8; u++) {
                unsigned long long wd = pk2(wi[u], wi[u]);
                fma2(p0, wd, pk2(xv[u].x, xv[u].y));
                fma2(p1, wd, pk2(xv[u].z, xv[u].w));
            }
        }
        for (; j < r1; j++) {
            int s0 = g_csrc[j];
            float w0 = g_cval[j];
            float4 x0 = *(const float4*)(g_xw + (size_t)s0 * HD + c4);
            unsigned long long wd0 = pk2(w0, w0);
            fma2(p0, wd0, pk2(x0.x, x0.y)); fma2(p1, wd0, pk2(x0.z, x0.w));
        }
        float2 e0 = up2(p0), e1 = up2(p1);
        float4 xs = *(const float4*)(g_xw + (size_t)v * HD + c4);
        float t2 = 2.f * dv * dv;
        float a0 = fmaf(dv, e0.x, fmaf(t2, xs.x, b4.x));
        float a1 = fmaf(dv, e0.y, fmaf(t2, xs.y, b4.y));
        float a2 = fmaf(dv, e1.x, fmaf(t2, xs.z, b4.z));
        float a3 = fmaf(dv, e1.y, fmaf(t2, xs.w, b4.w));
        *(float4*)(out + (size_t)v * HD + c4) = make_float4(a0, a1, a2, a3);
        ls0 += a0; ls1 += a1; ls2 += a2; ls3 += a3;
        lq0 = fmaf(a0, a0, lq0); lq1 = fmaf(a1, a1, lq1);
        lq2 = fmaf(a2, a2, lq2); lq3 = fmaf(a3, a3, lq3);
    }
    atomicAdd(&s_sum[c4 + 0], ls0); atomicAdd(&s_sum[c4 + 1], ls1);
    atomicAdd(&s_sum[c4 + 2], ls2); atomicAdd(&s_sum[c4 + 3], ls3);
    atomicAdd(&s_sq[c4 + 0], lq0);  atomicAdd(&s_sq[c4 + 1], lq1);
    atomicAdd(&s_sq[c4 + 2], lq2);  atomicAdd(&s_sq[c4 + 3], lq3);
    __syncthreads();
    if (tid < 128) {
        atomicAdd(&g_stats[layer][tid], s_sum[tid]);
        atomicAdd(&g_stats[layer][128 + tid], s_sq[tid]);
    }
    __threadfence();
    __syncthreads();
    if (tid == 0) {
        int p = atomicAdd(&g_done[layer], 1);
        s_last = (p == (int)gridDim.x - 1);
    }
    __syncthreads();
    if (s_last && tid < 128) {
        __threadfence();
        float sum = g_stats[layer][tid];
        float sq  = g_stats[layer][tid + 128];
        g_stats[layer][tid] = 0.f;
        g_stats[layer][tid + 128] = 0.f;
        if (tid == 0) g_done[layer] = 0;
        float inv_n = 1.0f / (float)n;
        float mean = sum * inv_n;
        float var  = fmaxf(sq * inv_n - mean * mean, 0.f);
        float s = bn_g[layer * HD + tid] * rsqrtf(var + 1e-5f);
        g_scale[layer][tid] = s;
        g_sbias[layer][tid] = bn_b[layer * HD + tid] - mean * s;
    }
}

// ---------------------------------------------------------------------------
// JK head + fused log_softmax, double-buffered BK=16 over concatenated K=640.
// B staged as pre-duplicated packed f32x2 pairs (no per-kstep pack MOVs).
__global__ __launch_bounds__(256, 2) void k_jk(const float* __restrict__ x,
                                               const float* __restrict__ fw,
                                               const float* __restrict__ fb,
                                               float* __restrict__ outp, int n) {
    __shared__ __align__(16) float As[2][16][128];
    __shared__ __align__(16) unsigned long long Bsd[2][16][40];
    __shared__ float bsum[40];
    int tid = threadIdx.x;
    if (tid < 40) {
        float b = 0.f;
        for (int i = 0; i < NLAY + 1; i++) b += fb[i * CD + tid];
        bsum[tid] = b;
    }
    int ar = tid >> 1, akq = (tid & 1) * 8;
    int trow = tid >> 3, tcol = tid & 7;
    int row0 = blockIdx.x * 128;
    int gr = row0 + ar;

    unsigned long long acc01[5], acc23[5];
#pragma unroll
    for (int c = 0; c < 5; c++) { acc01[c] = 0ull; acc23[c] = 0ull; }

    float4 pa[2], pbv;
    bool bldr = (tid < 160);
    int bkr = tid / 10, bnc = (tid % 10) * 4;

    auto load_slab = [&](int slab) {
        int k0 = slab * 16;
        int L = k0 >> 7;
        int kbase = k0 & 127;
        const float* A = (L == 0) ? x : g_agg[L - 1];
        pa[0] = make_float4(0.f, 0.f, 0.f, 0.f);
        pa[1] = pa[0];
        if (gr < n) {
            pa[0] = *(const float4*)(A + (size_t)gr * HD + kbase + akq);
            pa[1] = *(const float4*)(A + (size_t)gr * HD + kbase + akq + 4);
        }
        if (L > 0) {
#pragma unroll
            for (int h = 0; h < 2; h++) {
                int kk = kbase + akq + h * 4;
                float* p = (float*)&pa[h];
                p[0] = fmaxf(fmaf(p[0], g_scale[L - 1][kk + 0], g_sbias[L - 1][kk + 0]), 0.f);
                p[1] = fmaxf(fmaf(p[1], g_scale[L - 1][kk + 1], g_sbias[L - 1][kk + 1]), 0.f);
                p[2] = fmaxf(fmaf(p[2], g_scale[L - 1][kk + 2], g_sbias[L - 1][kk + 2]), 0.f);
                p[3] = fmaxf(fmaf(p[3], g_scale[L - 1][kk + 3], g_sbias[L - 1][kk + 3]), 0.f);
            }
        }
        if (bldr) {
            int kk = kbase + bkr;
            pbv = *(const float4*)(fw + ((size_t)L * HD + kk) * CD + bnc);
        }
    };
    auto store_slab = [&](int buf) {
#pragma unroll
        for (int h = 0; h < 2; h++) {
            float* p = (float*)&pa[h];
            As[buf][akq + h * 4 + 0][ar] = p[0];
            As[buf][akq + h * 4 + 1][ar] = p[1];
            As[buf][akq + h * 4 + 2][ar] = p[2];
            As[buf][akq + h * 4 + 3][ar] = p[3];
        }
        if (bldr) {
            Bsd[buf][bkr][bnc + 0] = pk2(pbv.x, pbv.x);
            Bsd[buf][bkr][bnc + 1] = pk2(pbv.y, pbv.y);
            Bsd[buf][bkr][bnc + 2] = pk2(pbv.z, pbv.z);
            Bsd[buf][bkr][bnc + 3] = pk2(pbv.w, pbv.w);
        }
    };

    load_slab(0);
    store_slab(0);
    __syncthreads();

    for (int slab = 0; slab < 40; slab++) {
        int buf = slab & 1;
        if (slab < 39) load_slab(slab + 1);
#pragma unroll
        for (int k = 0; k < 16; k++) {
            ulonglong2 apair = *(const ulonglong2*)&As[buf][k][trow * 4];
            unsigned long long bd[5];
#pragma unroll
            for (int c = 0; c < 5; c++) bd[c] = Bsd[buf][k][tcol * 5 + c];
#pragma unroll
            for (int c = 0; c < 5; c++) {
                fma2(acc01[c], apair.x, bd[c]);
                fma2(acc23[c], apair.y, bd[c]);
            }
        }
        if (slab < 39) {
            store_slab(buf ^ 1);
            __syncthreads();
        }
    }
    float v[4][5];
#pragma unroll
    for (int c = 0; c < 5; c++) {
        float2 r01 = up2(acc01[c]);
        float2 r23 = up2(acc23[c]);
        float bb = bsum[tcol * 5 + c];
        v[0][c] = r01.x + bb; v[1][c] = r01.y + bb;
        v[2][c] = r23.x + bb; v[3][c] = r23.y + bb;
    }
#pragma unroll
    for (int m = 0; m < 4; m++) {
        int r = row0 + trow * 4 + m;
        float mx = v[m][0];
#pragma unroll
        for (int c = 1; c < 5; c++) mx = fmaxf(mx, v[m][c]);
#pragma unroll
        for (int d = 1; d < 8; d <<= 1) mx = fmaxf(mx, __shfl_xor_sync(0xffffffffu, mx, d));
        float s = 0.f;
#pragma unroll
        for (int c = 0; c < 5; c++) s += expf(v[m][c] - mx);
#pragma unroll
        for (int d = 1; d < 8; d <<= 1) s += __shfl_xor_sync(0xffffffffu, s, d);
        float ls = mx + logf(s);
        if (r < n) {
#pragma unroll
            for (int c = 0; c < 5; c++)
                outp[(size_t)r * CD + tcol * 5 + c] = v[m][c] - ls;
        }
    }
}

// ---------------------------------------------------------------------------
extern "C" void kernel_launch(void* const* d_in, const int* in_sizes, int n_in,
                              void* d_out, int out_size) {
    const float* x      = (const float*)d_in[0];
    const int*   ei     = (const int*)d_in[1];
    const float* conv_w = (const float*)d_in[2];
    const float* conv_b = (const float*)d_in[3];
    const float* bn_g   = (const float*)d_in[4];
    const float* bn_b   = (const float*)d_in[5];
    const float* fc_w   = (const float*)d_in[6];
    const float* fc_b   = (const float*)d_in[7];
    int n = in_sizes[0] / FD;
    int e = in_sizes[1] / 2;
    const int* src = ei;
    const int* dst = ei + e;

    int gblocks = (n + 127) / 128;
    int hblocks = 512;

    // layer-0 GEMM fused with degree histogram (independent work overlapped)
    k_gemm<<<gblocks + hblocks, 256>>>(x, conv_w, 0, n, gblocks, dst, e);
    k_scan<<<1, 1024>>>(n);
    k_fill<<<(e + 255) / 256, 256>>>(src, dst, e);
    k_agg<<<1184, 256>>>(0, conv_b, bn_g, bn_b, n);

    for (int l = 1; l < NLAY; l++) {
        k_gemm<<<gblocks, 256>>>(x, conv_w + (size_t)l * FD * HD, l, n, gblocks, 0, 0);
        k_agg<<<1184, 256>>>(l, conv_b + (size_t)l * HD, bn_g, bn_b, n);
    }
    k_jk<<<gblocks, 256>>>(x, fc_w, fc_b, (float*)d_out, n);
}

// round 5
// speedup vs baseline: 1.0051x; 1.0051x over previous
#include <cuda_runtime.h>
#include <math.h>

#define NMAX 100000
#define EMAX 1600000
#define FD 128
#define HD 128
#define CD 40
#define NLAY 4

// ---- static device scratch ----
// Invariant: g_cnt, g_stats, g_done are zero at entry of every kernel_launch
// call (zero at module load; each call re-zeroes them after use).
__device__ float g_xw[(size_t)NMAX * HD];
__device__ float g_agg[NLAY][(size_t)NMAX * HD];
__device__ int   g_cnt[NMAX];
__device__ float g_dinv[NMAX];
__device__ int   g_off[NMAX + 1];
__device__ int   g_cur[NMAX];
__device__ int   g_csrc[EMAX];
__device__ float g_cval[EMAX];
__device__ float g_stats[NLAY][2 * HD];
__device__ float g_scale[NLAY][HD];
__device__ float g_sbias[NLAY][HD];
__device__ int   g_done[NLAY];

// ---- packed f32x2 helpers ----
__device__ __forceinline__ unsigned long long pk2(float lo, float hi) {
    unsigned long long r;
    asm("mov.b64 %0, {%1, %2};" : "=l"(r) : "f"(lo), "f"(hi));
    return r;
}
__device__ __forceinline__ void fma2(unsigned long long& d,
                                     unsigned long long a, unsigned long long b) {
    asm("fma.rn.f32x2 %0, %1, %2, %0;" : "+l"(d) : "l"(a), "l"(b));
}
__device__ __forceinline__ float2 up2(unsigned long long v) {
    float2 r;
    asm("mov.b64 {%0, %1}, %2;" : "=f"(r.x), "=f"(r.y) : "l"(v));
    return r;
}

// ---- tf32 helpers ----
__device__ __forceinline__ unsigned tf32_cvt(float f) {
    unsigned r;
    asm("cvt.rna.tf32.f32 %0, %1;" : "=r"(r) : "f"(f));
    return r;
}
__device__ __forceinline__ void mma_tf32(float* c, const unsigned* a, const unsigned* b) {
    asm("mma.sync.aligned.m16n8k8.row.col.f32.tf32.tf32.f32 "
        "{%0,%1,%2,%3}, {%4,%5,%6,%7}, {%8,%9}, {%0,%1,%2,%3};"
        : "+f"(c[0]), "+f"(c[1]), "+f"(c[2]), "+f"(c[3])
        : "r"(a[0]), "r"(a[1]), "r"(a[2]), "r"(a[3]), "r"(b[0]), "r"(b[1]));
}

// ---------------------------------------------------------------------------
__global__ void k_hist(const int* __restrict__ dst, int e) {
    int i = blockIdx.x * blockDim.x + threadIdx.x;
    if (i < e) atomicAdd(&g_cnt[dst[i]], 1);
}

// single-block scan: offsets, cursor init, dinv; zeroes g_cnt for next replay
__global__ void k_scan(int n) {
    __shared__ int sp[1024];
    int t = threadIdx.x;
    int chunk = (n + 1023) >> 10;
    int beg = t * chunk;
    int end = min(beg + chunk, n);
    int s = 0;
    for (int j = beg; j < end; j++) s += g_cnt[j];
    sp[t] = s;
    __syncthreads();
    for (int d = 1; d < 1024; d <<= 1) {
        int tmp = (t >= d) ? sp[t - d] : 0;
        __syncthreads();
        sp[t] += tmp;
        __syncthreads();
    }
    int base = sp[t] - s;
    for (int j = beg; j < end; j++) {
        int c = g_cnt[j];
        g_cnt[j] = 0;  // self-reset
        g_off[j] = base;
        g_cur[j] = base;
        g_dinv[j] = rsqrtf((float)c + 2.0f);
        base += c;
    }
    if (end == n) g_off[n] = base;
}

__global__ void k_fill(const int* __restrict__ src, const int* __restrict__ dst, int e) {
    int i = blockIdx.x * blockDim.x + threadIdx.x;
    if (i < e) {
        int d = dst[i];
        int s = src[i];
        int p = atomicAdd(&g_cur[d], 1);
        g_csrc[p] = s;
        g_cval[p] = g_dinv[s];
    }
}

// ---------------------------------------------------------------------------
// SGEMM via tf32 tensor cores with 3-term split (fp32-class accuracy):
//   D = Ahi*Bhi + Ahi*Blo + Alo*Bhi   (Alo*Blo term ~2^-22, negligible)
// g_xw[n,128] = A[n,128] @ W[128,128]; A = x or relu(bn(prev)) fused on load.
// 512 threads = 16 warps (4m x 4n), warp tile 32x32, m16n8k8 fragments.
__global__ __launch_bounds__(512, 1) void k_gemm(const float* __restrict__ x,
                                                 const float* __restrict__ W,
                                                 int layer, int n) {
    __shared__ __align__(16) float As[2][128][20];   // [buf][m][k] stride 20: conflict-free frags
    __shared__ __align__(16) float Bs[2][16][136];   // [buf][k][n] stride 136: conflict-free frags
    const float* A  = (layer == 0) ? x : g_agg[layer - 1];
    const float* sc = (layer > 0) ? g_scale[layer - 1] : 0;
    const float* sb = (layer > 0) ? g_sbias[layer - 1] : 0;
    int tid = threadIdx.x;
    int lane = tid & 31, wid = tid >> 5;
    int g4 = lane >> 2, t4 = lane & 3;
    int wr = (wid >> 2) * 32, wc = (wid & 3) * 32;
    int ar = tid >> 2, akq = (tid & 3) * 4;     // A staging: 1 float4/thread
    int bk = tid >> 5, bn0 = (tid & 31) * 4;    // B staging: 1 float4/thread
    int row0 = blockIdx.x * 128;
    int gr = row0 + ar;

    float acc[2][4][4];
#pragma unroll
    for (int mi = 0; mi < 2; mi++)
#pragma unroll
        for (int ni = 0; ni < 4; ni++)
#pragma unroll
            for (int q = 0; q < 4; q++) acc[mi][ni][q] = 0.f;

    float4 pa, pb;
    auto load_slab = [&](int s) {
        int k0 = s * 16;
        pa = make_float4(0.f, 0.f, 0.f, 0.f);
        if (gr < n) pa = *(const float4*)(A + (size_t)gr * HD + k0 + akq);
        if (layer > 0) {
            int kb = k0 + akq;
            pa.x = fmaxf(fmaf(pa.x, sc[kb + 0], sb[kb + 0]), 0.f);
            pa.y = fmaxf(fmaf(pa.y, sc[kb + 1], sb[kb + 1]), 0.f);
            pa.z = fmaxf(fmaf(pa.z, sc[kb + 2], sb[kb + 2]), 0.f);
            pa.w = fmaxf(fmaf(pa.w, sc[kb + 3], sb[kb + 3]), 0.f);
        }
        pb = *(const float4*)(W + (size_t)(k0 + bk) * HD + bn0);
    };
    auto store_slab = [&](int buf) {
        *(float4*)&As[buf][ar][akq] = pa;
        *(float4*)&Bs[buf][bk][bn0] = pb;
    };

    load_slab(0);
    store_slab(0);
    __syncthreads();

#pragma unroll
    for (int ks = 0; ks < 8; ks++) {
        int buf = ks & 1;
        if (ks < 7) load_slab(ks + 1);
#pragma unroll
        for (int kk = 0; kk < 2; kk++) {
            int kb = kk * 8;
            float af[2][4], bf[4][2];
#pragma unroll
            for (int mi = 0; mi < 2; mi++) {
                int m0 = wr + mi * 16 + g4;
                af[mi][0] = As[buf][m0][kb + t4];
                af[mi][1] = As[buf][m0 + 8][kb + t4];
                af[mi][2] = As[buf][m0][kb + 4 + t4];
                af[mi][3] = As[buf][m0 + 8][kb + 4 + t4];
            }
#pragma unroll
            for (int ni = 0; ni < 4; ni++) {
                int nn = wc + ni * 8 + g4;
                bf[ni][0] = Bs[buf][kb + t4][nn];
                bf[ni][1] = Bs[buf][kb + 4 + t4][nn];
            }
            unsigned ahi[2][4], bhi[4][2];
#pragma unroll
            for (int mi = 0; mi < 2; mi++)
#pragma unroll
                for (int q = 0; q < 4; q++) ahi[mi][q] = tf32_cvt(af[mi][q]);
#pragma unroll
            for (int ni = 0; ni < 4; ni++) {
                bhi[ni][0] = tf32_cvt(bf[ni][0]);
                bhi[ni][1] = tf32_cvt(bf[ni][1]);
            }
            // pass 1: Ahi * Bhi
#pragma unroll
            for (int mi = 0; mi < 2; mi++)
#pragma unroll
                for (int ni = 0; ni < 4; ni++)
                    mma_tf32(acc[mi][ni], ahi[mi], bhi[ni]);
            // pass 2: Ahi * Blo
            unsigned blo[4][2];
#pragma unroll
            for (int ni = 0; ni < 4; ni++) {
                blo[ni][0] = tf32_cvt(bf[ni][0] - __uint_as_float(bhi[ni][0]));
                blo[ni][1] = tf32_cvt(bf[ni][1] - __uint_as_float(bhi[ni][1]));
            }
#pragma unroll
            for (int mi = 0; mi < 2; mi++)
#pragma unroll
                for (int ni = 0; ni < 4; ni++)
                    mma_tf32(acc[mi][ni], ahi[mi], blo[ni]);
            // pass 3: Alo * Bhi
            unsigned alo[2][4];
#pragma unroll
            for (int mi = 0; mi < 2; mi++)
#pragma unroll
                for (int q = 0; q < 4; q++)
                    alo[mi][q] = tf32_cvt(af[mi][q] - __uint_as_float(ahi[mi][q]));
#pragma unroll
            for (int mi = 0; mi < 2; mi++)
#pragma unroll
                for (int ni = 0; ni < 4; ni++)
                    mma_tf32(acc[mi][ni], alo[mi], bhi[ni]);
        }
        if (ks < 7) {
            store_slab(buf ^ 1);
            __syncthreads();
        }
    }
    // epilogue: scatter C fragments
#pragma unroll
    for (int mi = 0; mi < 2; mi++) {
#pragma unroll
        for (int ni = 0; ni < 4; ni++) {
            int r = row0 + wr + mi * 16 + g4;
            int c = wc + ni * 8 + t4 * 2;
            if (r < n)
                *(float2*)(g_xw + (size_t)r * HD + c) =
                    make_float2(acc[mi][ni][0], acc[mi][ni][1]);
            if (r + 8 < n)
                *(float2*)(g_xw + (size_t)(r + 8) * HD + c) =
                    make_float2(acc[mi][ni][2], acc[mi][ni][3]);
        }
    }
}

// ---------------------------------------------------------------------------
// Aggregation: warp per node; lane owns 4 columns. Unroll-8 gather (MLP=8),
// contiguous csrc/cval streams. BN stats + fused scale/bias in last block.
__global__ __launch_bounds__(256) void k_agg(int layer, const float* __restrict__ convb,
                                             const float* __restrict__ bn_g,
                                             const float* __restrict__ bn_b, int n) {
    __shared__ float s_sum[128], s_sq[128];
    __shared__ int s_last;
    int tid = threadIdx.x;
    if (tid < 128) { s_sum[tid] = 0.f; s_sq[tid] = 0.f; }
    __syncthreads();

    int lane = tid & 31;
    int warp = tid >> 5;
    int c4 = lane * 4;
    float4 b4 = *(const float4*)(convb + c4);
    float* out = g_agg[layer];

    int gw = blockIdx.x * 8 + warp;
    int nw = gridDim.x * 8;

    float ls0 = 0.f, ls1 = 0.f, ls2 = 0.f, ls3 = 0.f;
    float lq0 = 0.f, lq1 = 0.f, lq2 = 0.f, lq3 = 0.f;

    for (int v = gw; v < n; v += nw) {
        int r0 = g_off[v], r1 = g_off[v + 1];
        float dv = g_dinv[v];
        unsigned long long p0 = 0ull, p1 = 0ull;
        int j = r0;
        for (; j + 7 < r1; j += 8) {
            int   si[8];
            float wi[8];
#pragma unroll
            for (int u = 0; u < 8; u++) { si[u] = g_csrc[j + u]; wi[u] = g_cval[j + u]; }
            float4 xv[8];
#pragma unroll
            for (int u = 0; u < 8; u++)
                xv[u] = *(const float4*)(g_xw + (size_t)si[u] * HD + c4);
#pragma unroll
            for (int u = 0; u < 8; u++) {
                unsigned long long wd = pk2(wi[u], wi[u]);
                fma2(p0, wd, pk2(xv[u].x, xv[u].y));
                fma2(p1, wd, pk2(xv[u].z, xv[u].w));
            }
        }
        for (; j < r1; j++) {
            int s0 = g_csrc[j];
            float w0 = g_cval[j];
            float4 x0 = *(const float4*)(g_xw + (size_t)s0 * HD + c4);
            unsigned long long wd0 = pk2(w0, w0);
            fma2(p0, wd0, pk2(x0.x, x0.y)); fma2(p1, wd0, pk2(x0.z, x0.w));
        }
        float2 e0 = up2(p0), e1 = up2(p1);
        float4 xs = *(const float4*)(g_xw + (size_t)v * HD + c4);
        float t2 = 2.f * dv * dv;
        float a0 = fmaf(dv, e0.x, fmaf(t2, xs.x, b4.x));
        float a1 = fmaf(dv, e0.y, fmaf(t2, xs.y, b4.y));
        float a2 = fmaf(dv, e1.x, fmaf(t2, xs.z, b4.z));
        float a3 = fmaf(dv, e1.y, fmaf(t2, xs.w, b4.w));
        *(float4*)(out + (size_t)v * HD + c4) = make_float4(a0, a1, a2, a3);
        ls0 += a0; ls1 += a1; ls2 += a2; ls3 += a3;
        lq0 = fmaf(a0, a0, lq0); lq1 = fmaf(a1, a1, lq1);
        lq2 = fmaf(a2, a2, lq2); lq3 = fmaf(a3, a3, lq3);
    }
    atomicAdd(&s_sum[c4 + 0], ls0); atomicAdd(&s_sum[c4 + 1], ls1);
    atomicAdd(&s_sum[c4 + 2], ls2); atomicAdd(&s_sum[c4 + 3], ls3);
    atomicAdd(&s_sq[c4 + 0], lq0);  atomicAdd(&s_sq[c4 + 1], lq1);
    atomicAdd(&s_sq[c4 + 2], lq2);  atomicAdd(&s_sq[c4 + 3], lq3);
    __syncthreads();
    if (tid < 128) {
        atomicAdd(&g_stats[layer][tid], s_sum[tid]);
        atomicAdd(&g_stats[layer][128 + tid], s_sq[tid]);
    }
    __threadfence();
    __syncthreads();
    if (tid == 0) {
        int p = atomicAdd(&g_done[layer], 1);
        s_last = (p == (int)gridDim.x - 1);
    }
    __syncthreads();
    if (s_last && tid < 128) {
        __threadfence();
        float sum = g_stats[layer][tid];
        float sq  = g_stats[layer][tid + 128];
        g_stats[layer][tid] = 0.f;
        g_stats[layer][tid + 128] = 0.f;
        if (tid == 0) g_done[layer] = 0;
        float inv_n = 1.0f / (float)n;
        float mean = sum * inv_n;
        float var  = fmaxf(sq * inv_n - mean * mean, 0.f);
        float s = bn_g[layer * HD + tid] * rsqrtf(var + 1e-5f);
        g_scale[layer][tid] = s;
        g_sbias[layer][tid] = bn_b[layer * HD + tid] - mean * s;
    }
}

// ---------------------------------------------------------------------------
// JK head + fused log_softmax, double-buffered BK=16 over concatenated K=640.
__global__ __launch_bounds__(256, 2) void k_jk(const float* __restrict__ x,
                                               const float* __restrict__ fw,
                                               const float* __restrict__ fb,
                                               float* __restrict__ outp, int n) {
    __shared__ __align__(16) float As[2][16][128];
    __shared__ __align__(16) unsigned long long Bsd[2][16][40];
    __shared__ float bsum[40];
    int tid = threadIdx.x;
    if (tid < 40) {
        float b = 0.f;
        for (int i = 0; i < NLAY + 1; i++) b += fb[i * CD + tid];
        bsum[tid] = b;
    }
    int ar = tid >> 1, akq = (tid & 1) * 8;
    int trow = tid >> 3, tcol = tid & 7;
    int row0 = blockIdx.x * 128;
    int gr = row0 + ar;

    unsigned long long acc01[5], acc23[5];
#pragma unroll
    for (int c = 0; c < 5; c++) { acc01[c] = 0ull; acc23[c] = 0ull; }

    float4 pa[2], pbv;
    bool bldr = (tid < 160);
    int bkr = tid / 10, bnc = (tid % 10) * 4;

    auto load_slab = [&](int slab) {
        int k0 = slab * 16;
        int L = k0 >> 7;
        int kbase = k0 & 127;
        const float* A = (L == 0) ? x : g_agg[L - 1];
        pa[0] = make_float4(0.f, 0.f, 0.f, 0.f);
        pa[1] = pa[0];
        if (gr < n) {
            pa[0] = *(const float4*)(A + (size_t)gr * HD + kbase + akq);
            pa[1] = *(const float4*)(A + (size_t)gr * HD + kbase + akq + 4);
        }
        if (L > 0) {
#pragma unroll
            for (int h = 0; h < 2; h++) {
                int kk = kbase + akq + h * 4;
                float* p = (float*)&pa[h];
                p[0] = fmaxf(fmaf(p[0], g_scale[L - 1][kk + 0], g_sbias[L - 1][kk + 0]), 0.f);
                p[1] = fmaxf(fmaf(p[1], g_scale[L - 1][kk + 1], g_sbias[L - 1][kk + 1]), 0.f);
                p[2] = fmaxf(fmaf(p[2], g_scale[L - 1][kk + 2], g_sbias[L - 1][kk + 2]), 0.f);
                p[3] = fmaxf(fmaf(p[3], g_scale[L - 1][kk + 3], g_sbias[L - 1][kk + 3]), 0.f);
            }
        }
        if (bldr) {
            int kk = kbase + bkr;
            pbv = *(const float4*)(fw + ((size_t)L * HD + kk) * CD + bnc);
        }
    };
    auto store_slab = [&](int buf) {
#pragma unroll
        for (int h = 0; h < 2; h++) {
            float* p = (float*)&pa[h];
            As[buf][akq + h * 4 + 0][ar] = p[0];
            As[buf][akq + h * 4 + 1][ar] = p[1];
            As[buf][akq + h * 4 + 2][ar] = p[2];
            As[buf][akq + h * 4 + 3][ar] = p[3];
        }
        if (bldr) {
            Bsd[buf][bkr][bnc + 0] = pk2(pbv.x, pbv.x);
            Bsd[buf][bkr][bnc + 1] = pk2(pbv.y, pbv.y);
            Bsd[buf][bkr][bnc + 2] = pk2(pbv.z, pbv.z);
            Bsd[buf][bkr][bnc + 3] = pk2(pbv.w, pbv.w);
        }
    };

    load_slab(0);
    store_slab(0);
    __syncthreads();

    for (int slab = 0; slab < 40; slab++) {
        int buf = slab & 1;
        if (slab < 39) load_slab(slab + 1);
#pragma unroll
        for (int k = 0; k < 16; k++) {
            ulonglong2 apair = *(const ulonglong2*)&As[buf][k][trow * 4];
            unsigned long long bd[5];
#pragma unroll
            for (int c = 0; c < 5; c++) bd[c] = Bsd[buf][k][tcol * 5 + c];
#pragma unroll
            for (int c = 0; c < 5; c++) {
                fma2(acc01[c], apair.x, bd[c]);
                fma2(acc23[c], apair.y, bd[c]);
            }
        }
        if (slab < 39) {
            store_slab(buf ^ 1);
            __syncthreads();
        }
    }
    float v[4][5];
#pragma unroll
    for (int c = 0; c < 5; c++) {
        float2 r01 = up2(acc01[c]);
        float2 r23 = up2(acc23[c]);
        float bb = bsum[tcol * 5 + c];
        v[0][c] = r01.x + bb; v[1][c] = r01.y + bb;
        v[2][c] = r23.x + bb; v[3][c] = r23.y + bb;
    }
#pragma unroll
    for (int m = 0; m < 4; m++) {
        int r = row0 + trow * 4 + m;
        float mx = v[m][0];
#pragma unroll
        for (int c = 1; c < 5; c++) mx = fmaxf(mx, v[m][c]);
#pragma unroll
        for (int d = 1; d < 8; d <<= 1) mx = fmaxf(mx, __shfl_xor_sync(0xffffffffu, mx, d));
        float s = 0.f;
#pragma unroll
        for (int c = 0; c < 5; c++) s += expf(v[m][c] - mx);
#pragma unroll
        for (int d = 1; d < 8; d <<= 1) s += __shfl_xor_sync(0xffffffffu, s, d);
        float ls = mx + logf(s);
        if (r < n) {
#pragma unroll
            for (int c = 0; c < 5; c++)
                outp[(size_t)r * CD + tcol * 5 + c] = v[m][c] - ls;
        }
    }
}

// ---------------------------------------------------------------------------
extern "C" void kernel_launch(void* const* d_in, const int* in_sizes, int n_in,
                              void* d_out, int out_size) {
    const float* x      = (const float*)d_in[0];
    const int*   ei     = (const int*)d_in[1];
    const float* conv_w = (const float*)d_in[2];
    const float* conv_b = (const float*)d_in[3];
    const float* bn_g   = (const float*)d_in[4];
    const float* bn_b   = (const float*)d_in[5];
    const float* fc_w   = (const float*)d_in[6];
    const float* fc_b   = (const float*)d_in[7];
    int n = in_sizes[0] / FD;
    int e = in_sizes[1] / 2;
    const int* src = ei;
    const int* dst = ei + e;

    k_hist<<<(e + 255) / 256, 256>>>(dst, e);
    k_scan<<<1, 1024>>>(n);
    k_fill<<<(e + 255) / 256, 256>>>(src, dst, e);

    int gblocks = (n + 127) / 128;
    for (int l = 0; l < NLAY; l++) {
        k_gemm<<<gblocks, 512>>>(x, conv_w + (size_t)l * FD * HD, l, n);
        k_agg<<<1184, 256>>>(l, conv_b + (size_t)l * HD, bn_g, bn_b, n);
    }
    k_jk<<<gblocks, 256>>>(x, fc_w, fc_b, (float*)d_out, n);
}

// round 6
// speedup vs baseline: 1.1323x; 1.1265x over previous
#include <cuda_runtime.h>
#include <math.h>

#define NMAX 100000
#define EMAX 1600000
#define FD 128
#define HD 128
#define CD 40
#define NLAY 4

// ---- static device scratch ----
// Invariant: g_cnt, g_stats, g_done are zero at entry of every kernel_launch
// call (zero at module load; each call re-zeroes them after use).
__device__ float g_xw[(size_t)NMAX * HD];
__device__ float g_agg[NLAY][(size_t)NMAX * HD];
__device__ int   g_cnt[NMAX];
__device__ float g_dinv[NMAX];
__device__ int   g_off[NMAX + 1];
__device__ int   g_cur[NMAX];
__device__ int   g_csrc[EMAX];
__device__ float g_cval[EMAX];
__device__ float g_stats[NLAY][2 * HD];
__device__ float g_scale[NLAY][HD];
__device__ float g_sbias[NLAY][HD];
__device__ int   g_done[NLAY];

// ---- packed f32x2 helpers ----
__device__ __forceinline__ unsigned long long pk2(float lo, float hi) {
    unsigned long long r;
    asm("mov.b64 %0, {%1, %2};" : "=l"(r) : "f"(lo), "f"(hi));
    return r;
}
__device__ __forceinline__ void fma2(unsigned long long& d,
                                     unsigned long long a, unsigned long long b) {
    asm("fma.rn.f32x2 %0, %1, %2, %0;" : "+l"(d) : "l"(a), "l"(b));
}
__device__ __forceinline__ float2 up2(unsigned long long v) {
    float2 r;
    asm("mov.b64 {%0, %1}, %2;" : "=f"(r.x), "=f"(r.y) : "l"(v));
    return r;
}

// ---- tf32 helpers ----
__device__ __forceinline__ unsigned tf32_cvt(float f) {
    unsigned r;
    asm("cvt.rna.tf32.f32 %0, %1;" : "=r"(r) : "f"(f));
    return r;
}
__device__ __forceinline__ void mma_tf32(float* c, const unsigned* a, const unsigned* b) {
    asm("mma.sync.aligned.m16n8k8.row.col.f32.tf32.tf32.f32 "
        "{%0,%1,%2,%3}, {%4,%5,%6,%7}, {%8,%9}, {%0,%1,%2,%3};"
        : "+f"(c[0]), "+f"(c[1]), "+f"(c[2]), "+f"(c[3])
        : "r"(a[0]), "r"(a[1]), "r"(a[2]), "r"(a[3]), "r"(b[0]), "r"(b[1]));
}

// ---------------------------------------------------------------------------
__global__ void k_hist(const int* __restrict__ dst, int e) {
    int i = blockIdx.x * blockDim.x + threadIdx.x;
    if (i < e) atomicAdd(&g_cnt[dst[i]], 1);
}

// single-block scan: offsets, cursor init, dinv; zeroes g_cnt for next replay
__global__ void k_scan(int n) {
    __shared__ int sp[1024];
    int t = threadIdx.x;
    int chunk = (n + 1023) >> 10;
    int beg = t * chunk;
    int end = min(beg + chunk, n);
    int s = 0;
    for (int j = beg; j < end; j++) s += g_cnt[j];
    sp[t] = s;
    __syncthreads();
    for (int d = 1; d < 1024; d <<= 1) {
        int tmp = (t >= d) ? sp[t - d] : 0;
        __syncthreads();
        sp[t] += tmp;
        __syncthreads();
    }
    int base = sp[t] - s;
    for (int j = beg; j < end; j++) {
        int c = g_cnt[j];
        g_cnt[j] = 0;  // self-reset
        g_off[j] = base;
        g_cur[j] = base;
        g_dinv[j] = rsqrtf((float)c + 2.0f);
        base += c;
    }
    if (end == n) g_off[n] = base;
}

__global__ void k_fill(const int* __restrict__ src, const int* __restrict__ dst, int e) {
    int i = blockIdx.x * blockDim.x + threadIdx.x;
    if (i < e) {
        int d = dst[i];
        int s = src[i];
        int p = atomicAdd(&g_cur[d], 1);
        g_csrc[p] = s;
        g_cval[p] = g_dinv[s];
    }
}

// ---------------------------------------------------------------------------
// SGEMM via tf32 tensor cores with 3-term split (fp32-class accuracy).
// g_xw[n,128] = A[n,128] @ W[128,128]; A = x or relu(bn(prev)) fused on load.
__global__ __launch_bounds__(512, 1) void k_gemm(const float* __restrict__ x,
                                                 const float* __restrict__ W,
                                                 int layer, int n) {
    __shared__ __align__(16) float As[2][128][20];
    __shared__ __align__(16) float Bs[2][16][136];
    const float* A  = (layer == 0) ? x : g_agg[layer - 1];
    const float* sc = (layer > 0) ? g_scale[layer - 1] : 0;
    const float* sb = (layer > 0) ? g_sbias[layer - 1] : 0;
    int tid = threadIdx.x;
    int lane = tid & 31, wid = tid >> 5;
    int g4 = lane >> 2, t4 = lane & 3;
    int wr = (wid >> 2) * 32, wc = (wid & 3) * 32;
    int ar = tid >> 2, akq = (tid & 3) * 4;
    int bk = tid >> 5, bn0 = (tid & 31) * 4;
    int row0 = blockIdx.x * 128;
    int gr = row0 + ar;

    float acc[2][4][4];
#pragma unroll
    for (int mi = 0; mi < 2; mi++)
#pragma unroll
        for (int ni = 0; ni < 4; ni++)
#pragma unroll
            for (int q = 0; q < 4; q++) acc[mi][ni][q] = 0.f;

    float4 pa, pb;
    auto load_slab = [&](int s) {
        int k0 = s * 16;
        pa = make_float4(0.f, 0.f, 0.f, 0.f);
        if (gr < n) pa = *(const float4*)(A + (size_t)gr * HD + k0 + akq);
        if (layer > 0) {
            int kb = k0 + akq;
            pa.x = fmaxf(fmaf(pa.x, sc[kb + 0], sb[kb + 0]), 0.f);
            pa.y = fmaxf(fmaf(pa.y, sc[kb + 1], sb[kb + 1]), 0.f);
            pa.z = fmaxf(fmaf(pa.z, sc[kb + 2], sb[kb + 2]), 0.f);
            pa.w = fmaxf(fmaf(pa.w, sc[kb + 3], sb[kb + 3]), 0.f);
        }
        pb = *(const float4*)(W + (size_t)(k0 + bk) * HD + bn0);
    };
    auto store_slab = [&](int buf) {
        *(float4*)&As[buf][ar][akq] = pa;
        *(float4*)&Bs[buf][bk][bn0] = pb;
    };

    load_slab(0);
    store_slab(0);
    __syncthreads();

#pragma unroll
    for (int ks = 0; ks < 8; ks++) {
        int buf = ks & 1;
        if (ks < 7) load_slab(ks + 1);
#pragma unroll
        for (int kk = 0; kk < 2; kk++) {
            int kb = kk * 8;
            float af[2][4], bf[4][2];
#pragma unroll
            for (int mi = 0; mi < 2; mi++) {
                int m0 = wr + mi * 16 + g4;
                af[mi][0] = As[buf][m0][kb + t4];
                af[mi][1] = As[buf][m0 + 8][kb + t4];
                af[mi][2] = As[buf][m0][kb + 4 + t4];
                af[mi][3] = As[buf][m0 + 8][kb + 4 + t4];
            }
#pragma unroll
            for (int ni = 0; ni < 4; ni++) {
                int nn = wc + ni * 8 + g4;
                bf[ni][0] = Bs[buf][kb + t4][nn];
                bf[ni][1] = Bs[buf][kb + 4 + t4][nn];
            }
            unsigned ahi[2][4], bhi[4][2];
#pragma unroll
            for (int mi = 0; mi < 2; mi++)
#pragma unroll
                for (int q = 0; q < 4; q++) ahi[mi][q] = tf32_cvt(af[mi][q]);
#pragma unroll
            for (int ni = 0; ni < 4; ni++) {
                bhi[ni][0] = tf32_cvt(bf[ni][0]);
                bhi[ni][1] = tf32_cvt(bf[ni][1]);
            }
#pragma unroll
            for (int mi = 0; mi < 2; mi++)
#pragma unroll
                for (int ni = 0; ni < 4; ni++)
                    mma_tf32(acc[mi][ni], ahi[mi], bhi[ni]);
            unsigned blo[4][2];
#pragma unroll
            for (int ni = 0; ni < 4; ni++) {
                blo[ni][0] = tf32_cvt(bf[ni][0] - __uint_as_float(bhi[ni][0]));
                blo[ni][1] = tf32_cvt(bf[ni][1] - __uint_as_float(bhi[ni][1]));
            }
#pragma unroll
            for (int mi = 0; mi < 2; mi++)
#pragma unroll
                for (int ni = 0; ni < 4; ni++)
                    mma_tf32(acc[mi][ni], ahi[mi], blo[ni]);
            unsigned alo[2][4];
#pragma unroll
            for (int mi = 0; mi < 2; mi++)
#pragma unroll
                for (int q = 0; q < 4; q++)
                    alo[mi][q] = tf32_cvt(af[mi][q] - __uint_as_float(ahi[mi][q]));
#pragma unroll
            for (int mi = 0; mi < 2; mi++)
#pragma unroll
                for (int ni = 0; ni < 4; ni++)
                    mma_tf32(acc[mi][ni], alo[mi], bhi[ni]);
        }
        if (ks < 7) {
            store_slab(buf ^ 1);
            __syncthreads();
        }
    }
#pragma unroll
    for (int mi = 0; mi < 2; mi++) {
#pragma unroll
        for (int ni = 0; ni < 4; ni++) {
            int r = row0 + wr + mi * 16 + g4;
            int c = wc + ni * 8 + t4 * 2;
            if (r < n)
                *(float2*)(g_xw + (size_t)r * HD + c) =
                    make_float2(acc[mi][ni][0], acc[mi][ni][1]);
            if (r + 8 < n)
                *(float2*)(g_xw + (size_t)(r + 8) * HD + c) =
                    make_float2(acc[mi][ni][2], acc[mi][ni][3]);
        }
    }
}

// ---------------------------------------------------------------------------
// Aggregation: warp per node; lane owns 4 columns. Unroll-8 gather,
// contiguous csrc/cval streams. BN stats + fused scale/bias in last block.
__global__ __launch_bounds__(256) void k_agg(int layer, const float* __restrict__ convb,
                                             const float* __restrict__ bn_g,
                                             const float* __restrict__ bn_b, int n) {
    __shared__ float s_sum[128], s_sq[128];
    __shared__ int s_last;
    int tid = threadIdx.x;
    if (tid < 128) { s_sum[tid] = 0.f; s_sq[tid] = 0.f; }
    __syncthreads();

    int lane = tid & 31;
    int warp = tid >> 5;
    int c4 = lane * 4;
    float4 b4 = *(const float4*)(convb + c4);
    float* out = g_agg[layer];

    int gw = blockIdx.x * 8 + warp;
    int nw = gridDim.x * 8;

    float ls0 = 0.f, ls1 = 0.f, ls2 = 0.f, ls3 = 0.f;
    float lq0 = 0.f, lq1 = 0.f, lq2 = 0.f, lq3 = 0.f;

    for (int v = gw; v < n; v += nw) {
        int r0 = g_off[v], r1 = g_off[v + 1];
        float dv = g_dinv[v];
        unsigned long long p0 = 0ull, p1 = 0ull;
        int j = r0;
        for (; j + 7 < r1; j += 8) {
            int   si[8];
            float wi[8];
#pragma unroll
            for (int u = 0; u < 8; u++) { si[u] = g_csrc[j + u]; wi[u] = g_cval[j + u]; }
            float4 xv[8];
#pragma unroll
            for (int u = 0; u < 8; u++)
                xv[u] = *(const float4*)(g_xw + (size_t)si[u] * HD + c4);
#pragma unroll
            for (int u = 0; u < 8; u++) {
                unsigned long long wd = pk2(wi[u], wi[u]);
                fma2(p0, wd, pk2(xv[u].x, xv[u].y));
                fma2(p1, wd, pk2(xv[u].z, xv[u].w));
            }
        }
        for (; j < r1; j++) {
            int s0 = g_csrc[j];
            float w0 = g_cval[j];
            float4 x0 = *(const float4*)(g_xw + (size_t)s0 * HD + c4);
            unsigned long long wd0 = pk2(w0, w0);
            fma2(p0, wd0, pk2(x0.x, x0.y)); fma2(p1, wd0, pk2(x0.z, x0.w));
        }
        float2 e0 = up2(p0), e1 = up2(p1);
        float4 xs = *(const float4*)(g_xw + (size_t)v * HD + c4);
        float t2 = 2.f * dv * dv;
        float a0 = fmaf(dv, e0.x, fmaf(t2, xs.x, b4.x));
        float a1 = fmaf(dv, e0.y, fmaf(t2, xs.y, b4.y));
        float a2 = fmaf(dv, e1.x, fmaf(t2, xs.z, b4.z));
        float a3 = fmaf(dv, e1.y, fmaf(t2, xs.w, b4.w));
        *(float4*)(out + (size_t)v * HD + c4) = make_float4(a0, a1, a2, a3);
        ls0 += a0; ls1 += a1; ls2 += a2; ls3 += a3;
        lq0 = fmaf(a0, a0, lq0); lq1 = fmaf(a1, a1, lq1);
        lq2 = fmaf(a2, a2, lq2); lq3 = fmaf(a3, a3, lq3);
    }
    atomicAdd(&s_sum[c4 + 0], ls0); atomicAdd(&s_sum[c4 + 1], ls1);
    atomicAdd(&s_sum[c4 + 2], ls2); atomicAdd(&s_sum[c4 + 3], ls3);
    atomicAdd(&s_sq[c4 + 0], lq0);  atomicAdd(&s_sq[c4 + 1], lq1);
    atomicAdd(&s_sq[c4 + 2], lq2);  atomicAdd(&s_sq[c4 + 3], lq3);
    __syncthreads();
    if (tid < 128) {
        atomicAdd(&g_stats[layer][tid], s_sum[tid]);
        atomicAdd(&g_stats[layer][128 + tid], s_sq[tid]);
    }
    __threadfence();
    __syncthreads();
    if (tid == 0) {
        int p = atomicAdd(&g_done[layer], 1);
        s_last = (p == (int)gridDim.x - 1);
    }
    __syncthreads();
    if (s_last && tid < 128) {
        __threadfence();
        float sum = g_stats[layer][tid];
        float sq  = g_stats[layer][tid + 128];
        g_stats[layer][tid] = 0.f;
        g_stats[layer][tid + 128] = 0.f;
        if (tid == 0) g_done[layer] = 0;
        float inv_n = 1.0f / (float)n;
        float mean = sum * inv_n;
        float var  = fmaxf(sq * inv_n - mean * mean, 0.f);
        float s = bn_g[layer * HD + tid] * rsqrtf(var + 1e-5f);
        g_scale[layer][tid] = s;
        g_sbias[layer][tid] = bn_b[layer * HD + tid] - mean * s;
    }
}

// ---------------------------------------------------------------------------
// JK head via tf32 tensor cores (3-term split) + fused bias + log_softmax.
// out[n,40] = log_softmax(sum_L relu_bn(h_L) @ fc_w[L] + sum_L fc_b[L]).
// 256 threads = 8 warps; warp = 16 rows x 40 cols (5 n8 tiles, A-frags reused).
// Double-buffered BK=16 slabs over concatenated K=640, BN+ReLU fused on A load.
__global__ __launch_bounds__(256, 2) void k_jk(const float* __restrict__ x,
                                               const float* __restrict__ fw,
                                               const float* __restrict__ fb,
                                               float* __restrict__ outp, int n) {
    __shared__ __align__(16) float As[2][128][20];  // [buf][m][k] pad 20
    __shared__ __align__(16) float Bs[2][16][44];   // [buf][k][n] pad 44 (conflict-free)
    __shared__ float bsum[40];
    int tid = threadIdx.x;
    int lane = tid & 31, wid = tid >> 5;
    int g4 = lane >> 2, t4 = lane & 3;
    int wr = wid * 16;
    int ar = tid >> 1, akq = (tid & 1) * 8;   // A staging: 2 float4/thread
    int row0 = blockIdx.x * 128;
    int gr = row0 + ar;
    bool bldr = (tid < 160);
    int bkr = tid / 10, bnc = (tid % 10) * 4;  // B staging: 1 float4 for tid<160

    if (tid < 40) {
        float b = 0.f;
        for (int i = 0; i < NLAY + 1; i++) b += fb[i * CD + tid];
        bsum[tid] = b;
    }

    float acc[5][4];
#pragma unroll
    for (int ni = 0; ni < 5; ni++)
#pragma unroll
        for (int q = 0; q < 4; q++) acc[ni][q] = 0.f;

    float4 pa[2], pbv;
    auto load_slab = [&](int slab) {
        int L = slab >> 3;
        int kbase = (slab & 7) * 16;
        const float* A = (L == 0) ? x : g_agg[L - 1];
        pa[0] = make_float4(0.f, 0.f, 0.f, 0.f);
        pa[1] = pa[0];
        if (gr < n) {
            pa[0] = *(const float4*)(A + (size_t)gr * HD + kbase + akq);
            pa[1] = *(const float4*)(A + (size_t)gr * HD + kbase + akq + 4);
        }
        if (L > 0) {
#pragma unroll
            for (int h = 0; h < 2; h++) {
                int kk = kbase + akq + h * 4;
                float* p = (float*)&pa[h];
                p[0] = fmaxf(fmaf(p[0], g_scale[L - 1][kk + 0], g_sbias[L - 1][kk + 0]), 0.f);
                p[1] = fmaxf(fmaf(p[1], g_scale[L - 1][kk + 1], g_sbias[L - 1][kk + 1]), 0.f);
                p[2] = fmaxf(fmaf(p[2], g_scale[L - 1][kk + 2], g_sbias[L - 1][kk + 2]), 0.f);
                p[3] = fmaxf(fmaf(p[3], g_scale[L - 1][kk + 3], g_sbias[L - 1][kk + 3]), 0.f);
            }
        }
        if (bldr) {
            int kk = kbase + bkr;
            pbv = *(const float4*)(fw + ((size_t)L * HD + kk) * CD + bnc);
        }
    };
    auto store_slab = [&](int buf) {
        *(float4*)&As[buf][ar][akq]     = pa[0];
        *(float4*)&As[buf][ar][akq + 4] = pa[1];
        if (bldr) *(float4*)&Bs[buf][bkr][bnc] = pbv;
    };

    load_slab(0);
    store_slab(0);
    __syncthreads();

    for (int slab = 0; slab < 40; slab++) {
        int buf = slab & 1;
        if (slab < 39) load_slab(slab + 1);
#pragma unroll
        for (int kk = 0; kk < 2; kk++) {
            int kb = kk * 8;
            float af[4];
            af[0] = As[buf][wr + g4][kb + t4];
            af[1] = As[buf][wr + 8 + g4][kb + t4];
            af[2] = As[buf][wr + g4][kb + 4 + t4];
            af[3] = As[buf][wr + 8 + g4][kb + 4 + t4];
            float bf[5][2];
#pragma unroll
            for (int ni = 0; ni < 5; ni++) {
                int nn = ni * 8 + g4;
                bf[ni][0] = Bs[buf][kb + t4][nn];
                bf[ni][1] = Bs[buf][kb + 4 + t4][nn];
            }
            unsigned ahi[4], bhi[5][2];
#pragma unroll
            for (int q = 0; q < 4; q++) ahi[q] = tf32_cvt(af[q]);
#pragma unroll
            for (int ni = 0; ni < 5; ni++) {
                bhi[ni][0] = tf32_cvt(bf[ni][0]);
                bhi[ni][1] = tf32_cvt(bf[ni][1]);
            }
#pragma unroll
            for (int ni = 0; ni < 5; ni++) mma_tf32(acc[ni], ahi, bhi[ni]);
            unsigned blo[5][2];
#pragma unroll
            for (int ni = 0; ni < 5; ni++) {
                blo[ni][0] = tf32_cvt(bf[ni][0] - __uint_as_float(bhi[ni][0]));
                blo[ni][1] = tf32_cvt(bf[ni][1] - __uint_as_float(bhi[ni][1]));
            }
#pragma unroll
            for (int ni = 0; ni < 5; ni++) mma_tf32(acc[ni], ahi, blo[ni]);
            unsigned alo[4];
#pragma unroll
            for (int q = 0; q < 4; q++)
                alo[q] = tf32_cvt(af[q] - __uint_as_float(ahi[q]));
#pragma unroll
            for (int ni = 0; ni < 5; ni++) mma_tf32(acc[ni], alo, bhi[ni]);
        }
        if (slab < 39) {
            store_slab(buf ^ 1);
            __syncthreads();
        }
    }

    // epilogue: bias + per-row log_softmax. Lane owns rows (wr+g4, wr+8+g4),
    // cols ni*8 + t4*2 (+1). Row reduction = shfl_xor over t4 (masks 1,2).
#pragma unroll
    for (int half = 0; half < 2; half++) {
        float v[5][2];
#pragma unroll
        for (int ni = 0; ni < 5; ni++) {
            float b0 = bsum[ni * 8 + t4 * 2];
            float b1 = bsum[ni * 8 + t4 * 2 + 1];
            v[ni][0] = acc[ni][half * 2 + 0] + b0;
            v[ni][1] = acc[ni][half * 2 + 1] + b1;
        }
        float mx = v[0][0];
#pragma unroll
        for (int ni = 0; ni < 5; ni++) {
            mx = fmaxf(mx, v[ni][0]);
            mx = fmaxf(mx, v[ni][1]);
        }
        mx = fmaxf(mx, __shfl_xor_sync(0xffffffffu, mx, 1));
        mx = fmaxf(mx, __shfl_xor_sync(0xffffffffu, mx, 2));
        float s = 0.f;
#pragma unroll
        for (int ni = 0; ni < 5; ni++)
            s += expf(v[ni][0] - mx) + expf(v[ni][1] - mx);
        s += __shfl_xor_sync(0xffffffffu, s, 1);
        s += __shfl_xor_sync(0xffffffffu, s, 2);
        float ls = mx + logf(s);
        int r = row0 + wr + half * 8 + g4;
        if (r < n) {
#pragma unroll
            for (int ni = 0; ni < 5; ni++)
                *(float2*)(outp + (size_t)r * CD + ni * 8 + t4 * 2) =
                    make_float2(v[ni][0] - ls, v[ni][1] - ls);
        }
    }
}

// ---------------------------------------------------------------------------
extern "C" void kernel_launch(void* const* d_in, const int* in_sizes, int n_in,
                              void* d_out, int out_size) {
    const float* x      = (const float*)d_in[0];
    const int*   ei     = (const int*)d_in[1];
    const float* conv_w = (const float*)d_in[2];
    const float* conv_b = (const float*)d_in[3];
    const float* bn_g   = (const float*)d_in[4];
    const float* bn_b   = (const float*)d_in[5];
    const float* fc_w   = (const float*)d_in[6];
    const float* fc_b   = (const float*)d_in[7];
    int n = in_sizes[0] / FD;
    int e = in_sizes[1] / 2;
    const int* src = ei;
    const int* dst = ei + e;

    k_hist<<<(e + 255) / 256, 256>>>(dst, e);
    k_scan<<<1, 1024>>>(n);
    k_fill<<<(e + 255) / 256, 256>>>(src, dst, e);

    int gblocks = (n + 127) / 128;
    for (int l = 0; l < NLAY; l++) {
        k_gemm<<<gblocks, 512>>>(x, conv_w + (size_t)l * FD * HD, l, n);
        k_agg<<<1184, 256>>>(l, conv_b + (size_t)l * HD, bn_g, bn_b, n);
    }
    k_jk<<<gblocks, 256>>>(x, fc_w, fc_b, (float*)d_out, n);
}